// round 9
// baseline (speedup 1.0000x reference)
#include <cuda_runtime.h>
#include <cstdint>
#include <cstddef>

#define K3   27
#define PPK  131072
#define NVOX 262144
#define CIN  32
#define COUT 32
#define TPB  128
#define TILE 128
#define QSCALE 32512.0f
#define BIAS_BLOCKS 8192   // NVOX*8/256

// Pre-built int8 mma B fragments: [ko][ng][lane] = {b0hi, b1hi, b0lo, b1lo}
__device__ __align__(16) uint4 Wfrag8[K3 * 4 * 32];
__device__ float invT_g[K3 * 32];

// ---------- helpers ----------
__device__ __forceinline__ unsigned pack4(int a, int b, int c, int d) {
    return (unsigned)(a & 0xff) | ((unsigned)(b & 0xff) << 8) |
           ((unsigned)(c & 0xff) << 16) | ((unsigned)(d & 0xff) << 24);
}
__device__ __forceinline__ void red4(float* p, float a, float b, float c, float d) {
    asm volatile("red.global.add.v4.f32 [%0], {%1, %2, %3, %4};"
                 :: "l"(p), "f"(a), "f"(b), "f"(c), "f"(d) : "memory");
}
__device__ __forceinline__ void mma_s8(int c[4],
                                       unsigned a0, unsigned a1, unsigned a2, unsigned a3,
                                       unsigned b0, unsigned b1) {
    asm volatile(
        "mma.sync.aligned.m16n8k32.row.col.s32.s8.s8.s32 "
        "{%0,%1,%2,%3}, {%4,%5,%6,%7}, {%8,%9}, {%0,%1,%2,%3};"
        : "+r"(c[0]), "+r"(c[1]), "+r"(c[2]), "+r"(c[3])
        : "r"(a0), "r"(a1), "r"(a2), "r"(a3), "r"(b0), "r"(b1));
}

// ---------- merged prep: bias init + W quantize/fragment ----------
__global__ __launch_bounds__(256) void prep_kernel(
    const float* __restrict__ Wg, const float* __restrict__ bias,
    float4* __restrict__ out) {
    const int bid = blockIdx.x;
    const int t = threadIdx.x;
    if (bid < BIAS_BLOCKS) {
        int idx = bid * 256 + t;
        float4 b = __ldg(((const float4*)bias) + (idx & 7));
        out[idx] = b;
        return;
    }
    const int ko = bid - BIAS_BLOCKS;
    const float* w = Wg + ko * 1024;
    __shared__ float Ts[32];
    if (t < 32) {
        float m = 0.0f;
        for (int k = 0; k < 32; k++) m = fmaxf(m, fabsf(__ldg(w + k * 32 + t)));
        m = fmaxf(m, 1e-20f);
        Ts[t] = QSCALE / m;
        invT_g[ko * 32 + t] = m * (1.0f / QSCALE);
    }
    __syncthreads();
    if (t < 128) {
        int ng = t >> 5, lane = t & 31;
        int col = ng * 8 + (lane >> 2);
        int k0 = (lane & 3) * 4;
        float T = Ts[col];
        int hi[8], lo[8];
#pragma unroll
        for (int j = 0; j < 8; j++) {
            int k = (j < 4) ? (k0 + j) : (16 + k0 + (j - 4));
            int v = __float2int_rn(__ldg(w + k * 32 + col) * T);
            hi[j] = (v + 128) >> 8;
            lo[j] = v - (hi[j] << 8);
        }
        Wfrag8[(ko * 4 + ng) * 32 + lane] =
            make_uint4(pack4(hi[0], hi[1], hi[2], hi[3]),
                       pack4(hi[4], hi[5], hi[6], hi[7]),
                       pack4(lo[0], lo[1], lo[2], lo[3]),
                       pack4(lo[4], lo[5], lo[6], lo[7]));
    }
}

// ---------- main conv ----------
__global__ __launch_bounds__(TPB, 6) void conv_i8_kernel(
    const float4* __restrict__ in_f4,
    const int2*   __restrict__ nbmap2,
    float*        __restrict__ out) {

    __shared__ __align__(16) char A_s[TILE * 96];     // 12KB: int8 hi|lo rows
    __shared__ __align__(16) char C_s[4 * 16 * 128];  // 8KB: per-warp C staging
    __shared__ int   src_s[TILE];
    __shared__ int   dst_s[TILE];
    __shared__ float srow_s[TILE];

    const int t = threadIdx.x;
    const int lane = t & 31;
    const int wid = t >> 5;
    const int ko = blockIdx.y;
    const long base = (long)ko * PPK + (long)blockIdx.x * TILE;

    // nbmap tile
    {
        int2 a = __ldg(nbmap2 + base + t);
        src_s[t] = a.x; dst_s[t] = a.y;
    }

    // B fragments + column scales (registers for whole kernel)
    uint4 bf[4];
    float invT0[4], invT1[4];
    {
        int nc0 = (lane & 3) * 2;
#pragma unroll
        for (int ng = 0; ng < 4; ng++) {
            bf[ng] = __ldg(&Wfrag8[(ko * 4 + ng) * 32 + lane]);
            invT0[ng] = __ldg(&invT_g[ko * 32 + ng * 8 + nc0]);
            invT1[ng] = __ldg(&invT_g[ko * 32 + ng * 8 + nc0 + 1]);
        }
    }
    __syncthreads();

    // ---- coalesced gather + per-row quantize + conflict-free STS ----
#pragma unroll
    for (int j = 0; j < 8; j++) {
        int idx = j * TPB + t;           // 1024 = 128 rows x 8 chunks
        int r = idx >> 3;
        int c = idx & 7;
        float4 v = __ldg(in_f4 + (size_t)src_s[r] * 8 + c);
        float m = fmaxf(fmaxf(fabsf(v.x), fabsf(v.y)), fmaxf(fabsf(v.z), fabsf(v.w)));
        m = fmaxf(m, __shfl_xor_sync(0xffffffffu, m, 1));
        m = fmaxf(m, __shfl_xor_sync(0xffffffffu, m, 2));
        m = fmaxf(m, __shfl_xor_sync(0xffffffffu, m, 4));
        m = fmaxf(m, 1e-20f);
        float S = QSCALE / m;
        if (c == 0) srow_s[r] = m * (1.0f / QSCALE);
        int v0 = __float2int_rn(v.x * S);
        int v1 = __float2int_rn(v.y * S);
        int v2 = __float2int_rn(v.z * S);
        int v3 = __float2int_rn(v.w * S);
        int h0 = (v0 + 128) >> 8, h1 = (v1 + 128) >> 8;
        int h2 = (v2 + 128) >> 8, h3 = (v3 + 128) >> 8;
        unsigned hp = pack4(h0, h1, h2, h3);
        unsigned lp = pack4(v0 - (h0 << 8), v1 - (h1 << 8),
                            v2 - (h2 << 8), v3 - (h3 << 8));
        int slot = (c ^ (r & 4));
        *(unsigned*)(A_s + r * 96 + slot * 4)      = hp;
        *(unsigned*)(A_s + r * 96 + 32 + slot * 4) = lp;
    }
    __syncthreads();

    char* Cw = C_s + wid * 2048;
    const int qr = lane >> 2;
    const int qq = lane & 3;

#pragma unroll
    for (int mg = 0; mg < 2; mg++) {
        const int mgbase = wid * 32 + mg * 16;
        const int ra = mgbase + qr;       // rows ra, ra+8
        const int s4 = ra & 4;            // (ra+8)&4 == ra&4

        // A fragments (conflict-free LDS.32)
        unsigned ah[4], al[4];
        {
            const char* r0p = A_s + ra * 96;
            const char* r1p = A_s + (ra + 8) * 96;
            int g0 = qq ^ s4;
            int g1 = (4 + qq) ^ s4;
            ah[0] = *(const unsigned*)(r0p + g0 * 4);
            ah[1] = *(const unsigned*)(r1p + g0 * 4);
            ah[2] = *(const unsigned*)(r0p + g1 * 4);
            ah[3] = *(const unsigned*)(r1p + g1 * 4);
            al[0] = *(const unsigned*)(r0p + 32 + g0 * 4);
            al[1] = *(const unsigned*)(r1p + 32 + g0 * 4);
            al[2] = *(const unsigned*)(r0p + 32 + g1 * 4);
            al[3] = *(const unsigned*)(r1p + 32 + g1 * 4);
        }

        int chh[4][4], cmix[4][4];
#pragma unroll
        for (int ng = 0; ng < 4; ng++)
#pragma unroll
            for (int i = 0; i < 4; i++) { chh[ng][i] = 0; cmix[ng][i] = 0; }

#pragma unroll
        for (int ng = 0; ng < 4; ng++) {
            mma_s8(chh[ng],  ah[0], ah[1], ah[2], ah[3], bf[ng].x, bf[ng].y); // Ah*Bh
            mma_s8(cmix[ng], ah[0], ah[1], ah[2], ah[3], bf[ng].z, bf[ng].w); // Ah*Bl
            mma_s8(cmix[ng], al[0], al[1], al[2], al[3], bf[ng].x, bf[ng].y); // Al*Bh
        }

        // epilogue: dequantize + stage into C smem (swizzled 128B rows)
        float is0 = srow_s[ra];
        float is1 = srow_s[ra + 8];
#pragma unroll
        for (int ng = 0; ng < 4; ng++) {
            float t00 = is0 * invT0[ng], t01 = is0 * invT1[ng];
            float t10 = is1 * invT0[ng], t11 = is1 * invT1[ng];
            float v00 = (65536.f * (float)chh[ng][0] + 256.f * (float)cmix[ng][0]) * t00;
            float v01 = (65536.f * (float)chh[ng][1] + 256.f * (float)cmix[ng][1]) * t01;
            float v10 = (65536.f * (float)chh[ng][2] + 256.f * (float)cmix[ng][2]) * t10;
            float v11 = (65536.f * (float)chh[ng][3] + 256.f * (float)cmix[ng][3]) * t11;
            int chunk = ng * 2 + (qq >> 1);
            int sub = (qq & 1) * 8;
            *(float2*)(Cw + qr * 128 + ((chunk ^ qr) << 4) + sub)       = make_float2(v00, v01);
            *(float2*)(Cw + (qr + 8) * 128 + ((chunk ^ qr) << 4) + sub) = make_float2(v10, v11);
        }
        __syncwarp();

        // coalesced scatter: 8 lanes cover one 128B dst row
#pragma unroll
        for (int j = 0; j < 4; j++) {
            int idx = j * 32 + lane;      // 128 = 16 rows x 8 chunks
            int lr = idx >> 3;
            int q = idx & 7;
            int cc = q ^ (lr & 7);
            float4 v = *(const float4*)(Cw + lr * 128 + q * 16);
            red4(out + (size_t)dst_s[mgbase + lr] * COUT + cc * 4, v.x, v.y, v.z, v.w);
        }
        __syncwarp();
    }
}

extern "C" void kernel_launch(void* const* d_in, const int* in_sizes, int n_in,
                              void* d_out, int out_size) {
    const float* in_f  = (const float*)d_in[0];   // [262144, 32] f32
    const float* W     = (const float*)d_in[1];   // [27, 32, 32] f32
    const float* bias  = (const float*)d_in[2];   // [32] f32
    const int*   nbmap = (const int*)d_in[3];     // [M, 2] i32
    float*       out   = (float*)d_out;           // [262144, 32] f32
    (void)in_sizes; (void)n_in; (void)out_size;

    prep_kernel<<<BIAS_BLOCKS + K3, 256>>>(W, bias, (float4*)out);

    dim3 grid(PPK / TILE, K3);
    conv_i8_kernel<<<grid, TPB>>>((const float4*)in_f, (const int2*)nbmap, out);
}

// round 11
// speedup vs baseline: 1.5328x; 1.5328x over previous
#include <cuda_runtime.h>
#include <cstdint>
#include <cstddef>

#define K3   27
#define PPK  131072
#define NVOX 262144
#define CIN  32
#define COUT 32
#define TPB  128
#define TILE 128
#define BIAS_BLOCKS 8192   // NVOX*8/256

// Pre-built fp16 mma B fragments: [ko][ng][lane] = {b0_kg0, b1_kg0, b0_kg1, b1_kg1}
__device__ __align__(16) uint4 Wfrag16[K3 * 4 * 32];

// ---------- helpers ----------
// pack (a,b) -> f16x2, a in LOW half
__device__ __forceinline__ unsigned pk_f16(float a, float b) {
    unsigned r;
    asm("cvt.rn.f16x2.f32 %0, %1, %2;" : "=r"(r) : "f"(b), "f"(a));
    return r;
}
__device__ __forceinline__ void red4(float* p, float a, float b, float c, float d) {
    asm volatile("red.global.add.v4.f32 [%0], {%1, %2, %3, %4};"
                 :: "l"(p), "f"(a), "f"(b), "f"(c), "f"(d) : "memory");
}
__device__ __forceinline__ void ldsm4(unsigned &r0, unsigned &r1, unsigned &r2, unsigned &r3,
                                      unsigned addr) {
    asm volatile("ldmatrix.sync.aligned.m8n8.x4.shared.b16 {%0,%1,%2,%3}, [%4];"
                 : "=r"(r0), "=r"(r1), "=r"(r2), "=r"(r3) : "r"(addr));
}
__device__ __forceinline__ void mma_f16(float c[4],
                                        unsigned a0, unsigned a1, unsigned a2, unsigned a3,
                                        unsigned b0, unsigned b1) {
    asm volatile(
        "mma.sync.aligned.m16n8k16.row.col.f32.f16.f16.f32 "
        "{%0,%1,%2,%3}, {%4,%5,%6,%7}, {%8,%9}, {%0,%1,%2,%3};"
        : "+f"(c[0]), "+f"(c[1]), "+f"(c[2]), "+f"(c[3])
        : "r"(a0), "r"(a1), "r"(a2), "r"(a3), "r"(b0), "r"(b1));
}
__device__ __forceinline__ unsigned smem_u32(const void* p) {
    unsigned a;
    asm("{ .reg .u64 t; cvta.to.shared.u64 t, %1; cvt.u32.u64 %0, t; }" : "=r"(a) : "l"(p));
    return a;
}

// A tile addressing: logical row r (0..127) = 64B, packed 2 rows per 128B phys row.
// granule slot g (0..3, 16B each) swizzled by (r>>1)&3.
__device__ __forceinline__ unsigned a_addr(int r, int g) {
    return (unsigned)(((r >> 1) * 128) + ((r & 1) * 64) + ((g ^ ((r >> 1) & 3)) << 4));
}

// ---------- merged prep: bias init + W fp16 fragment build ----------
__global__ __launch_bounds__(256) void prep_kernel(
    const float* __restrict__ Wg, const float* __restrict__ bias,
    float4* __restrict__ out) {
    const int bid = blockIdx.x;
    const int t = threadIdx.x;
    if (bid < BIAS_BLOCKS) {
        int idx = bid * 256 + t;
        float4 b = __ldg(((const float4*)bias) + (idx & 7));
        out[idx] = b;
        return;
    }
    const int ko = bid - BIAS_BLOCKS;
    const float* w = Wg + ko * 1024;
    if (t < 128) {
        int ng = t >> 5, lane = t & 31;
        int q = lane & 3;
        int n = ng * 8 + (lane >> 2);
        unsigned b[4];
#pragma unroll
        for (int kg = 0; kg < 2; kg++) {
            int k0 = kg * 16 + q * 2;
            b[2 * kg + 0] = pk_f16(__ldg(w + (k0 + 0) * 32 + n), __ldg(w + (k0 + 1) * 32 + n));
            b[2 * kg + 1] = pk_f16(__ldg(w + (k0 + 8) * 32 + n), __ldg(w + (k0 + 9) * 32 + n));
        }
        Wfrag16[(ko * 4 + ng) * 32 + lane] = make_uint4(b[0], b[1], b[2], b[3]);
    }
}

// ---------- main conv ----------
__global__ __launch_bounds__(TPB, 7) void conv_f16_kernel(
    const float4* __restrict__ in_f4,
    const int2*   __restrict__ nbmap2,
    float*        __restrict__ out) {

    __shared__ __align__(128) char A_s[64 * 128];   // 8KB: 128 logical rows x 64B fp16
    __shared__ int src_s[TILE];
    __shared__ int dst_s[TILE];

    const int t = threadIdx.x;
    const int lane = t & 31;
    const int wid = t >> 5;
    const int ko = blockIdx.y;
    const long base = (long)ko * PPK + (long)blockIdx.x * TILE;

    // nbmap tile
    {
        int2 a = __ldg(nbmap2 + base + t);
        src_s[t] = a.x; dst_s[t] = a.y;
    }

    // W fragments (registers for whole kernel)
    uint4 bf[4];
#pragma unroll
    for (int ng = 0; ng < 4; ng++)
        bf[ng] = __ldg(&Wfrag16[(ko * 4 + ng) * 32 + lane]);
    __syncthreads();

    // ---- coalesced gather + fp16 convert + swizzled STS (2-way optimal) ----
#pragma unroll
    for (int j = 0; j < 8; j++) {
        int idx = j * TPB + t;          // 1024 = 128 rows x 8 float4-chunks
        int r = idx >> 3;
        int c = idx & 7;
        float4 v = __ldg(in_f4 + (size_t)src_s[r] * 8 + c);
        unsigned h01 = pk_f16(v.x, v.y);
        unsigned h23 = pk_f16(v.z, v.w);
        *(uint2*)(A_s + a_addr(r, c >> 1) + (c & 1) * 8) = make_uint2(h01, h23);
    }
    __syncthreads();

    const unsigned asb = smem_u32(A_s);
    const int mrow = ((lane >> 3) & 1) * 8 + (lane & 7);
    const int csel = lane >> 4;          // which 16B granule of the k16 slice
    const int qr = lane >> 2;
    const int qq = lane & 3;
    const int wbase = wid * 32;

    // ---- load ALL A fragments first (A region reused for C after) ----
    unsigned af[2][2][4];                // [mg][kg][4]
#pragma unroll
    for (int mg = 0; mg < 2; mg++) {
#pragma unroll
        for (int kg = 0; kg < 2; kg++) {
            int row = wbase + mg * 16 + mrow;
            ldsm4(af[mg][kg][0], af[mg][kg][1], af[mg][kg][2], af[mg][kg][3],
                  asb + a_addr(row, kg * 2 + csel));
        }
    }

    // ---- 16 MMAs ----
    float c[2][4][4];
#pragma unroll
    for (int mg = 0; mg < 2; mg++)
#pragma unroll
        for (int ng = 0; ng < 4; ng++) {
#pragma unroll
            for (int i = 0; i < 4; i++) c[mg][ng][i] = 0.0f;
            mma_f16(c[mg][ng], af[mg][0][0], af[mg][0][1], af[mg][0][2], af[mg][0][3],
                    bf[ng].x, bf[ng].y);
            mma_f16(c[mg][ng], af[mg][1][0], af[mg][1][1], af[mg][1][2], af[mg][1][3],
                    bf[ng].z, bf[ng].w);
        }

    // ---- per mg: stage C into warp's (consumed) A region, then scatter ----
    char* Cw = A_s + wid * 2048;         // 16 rows x 128B
    __syncwarp();
#pragma unroll
    for (int mg = 0; mg < 2; mg++) {
        const int mgbase = wbase + mg * 16;
#pragma unroll
        for (int ng = 0; ng < 4; ng++) {
            int chunk = ng * 2 + (qq >> 1);
            int sub = (qq & 1) * 8;
            *(float2*)(Cw + qr * 128 + ((chunk ^ qr) << 4) + sub) =
                make_float2(c[mg][ng][0], c[mg][ng][1]);
            *(float2*)(Cw + (qr + 8) * 128 + ((chunk ^ qr) << 4) + sub) =
                make_float2(c[mg][ng][2], c[mg][ng][3]);
        }
        __syncwarp();

        // coalesced scatter: 8 lanes cover one 128B dst row
#pragma unroll
        for (int j = 0; j < 4; j++) {
            int idx = j * 32 + lane;     // 128 = 16 rows x 8 chunks
            int lr = idx >> 3;
            int q = idx & 7;
            int cc = q ^ (lr & 7);
            float4 v = *(const float4*)(Cw + lr * 128 + q * 16);
            red4(out + (size_t)dst_s[mgbase + lr] * COUT + cc * 4, v.x, v.y, v.z, v.w);
        }
        __syncwarp();
    }
}

extern "C" void kernel_launch(void* const* d_in, const int* in_sizes, int n_in,
                              void* d_out, int out_size) {
    const float* in_f  = (const float*)d_in[0];   // [262144, 32] f32
    const float* W     = (const float*)d_in[1];   // [27, 32, 32] f32
    const float* bias  = (const float*)d_in[2];   // [32] f32
    const int*   nbmap = (const int*)d_in[3];     // [M, 2] i32
    float*       out   = (float*)d_out;           // [262144, 32] f32
    (void)in_sizes; (void)n_in; (void)out_size;

    prep_kernel<<<BIAS_BLOCKS + K3, 256>>>(W, bias, (float4*)out);

    dim3 grid(PPK / TILE, K3);
    conv_f16_kernel<<<grid, TPB>>>((const float4*)in_f, (const int2*)nbmap, out);
}

// round 12
// speedup vs baseline: 1.6304x; 1.0637x over previous
#include <cuda_runtime.h>
#include <cstdint>
#include <cstddef>

#define K3   27
#define PPK  131072
#define NVOX 262144
#define CIN  32
#define COUT 32
#define TPB  128
#define TILE 256      // two 128-pair subtiles per block (pipelined)
#define BIAS_BLOCKS 8192   // NVOX*8/256

// Pre-built fp16 mma B fragments: [ko][ng][lane] = {b0_kg0, b1_kg0, b0_kg1, b1_kg1}
__device__ __align__(16) uint4 Wfrag16[K3 * 4 * 32];

// ---------- helpers ----------
// pack (a,b) -> f16x2, a in LOW half
__device__ __forceinline__ unsigned pk_f16(float a, float b) {
    unsigned r;
    asm("cvt.rn.f16x2.f32 %0, %1, %2;" : "=r"(r) : "f"(b), "f"(a));
    return r;
}
__device__ __forceinline__ void red4(float* p, float a, float b, float c, float d) {
    asm volatile("red.global.add.v4.f32 [%0], {%1, %2, %3, %4};"
                 :: "l"(p), "f"(a), "f"(b), "f"(c), "f"(d) : "memory");
}
__device__ __forceinline__ void ldsm4(unsigned &r0, unsigned &r1, unsigned &r2, unsigned &r3,
                                      unsigned addr) {
    asm volatile("ldmatrix.sync.aligned.m8n8.x4.shared.b16 {%0,%1,%2,%3}, [%4];"
                 : "=r"(r0), "=r"(r1), "=r"(r2), "=r"(r3) : "r"(addr));
}
__device__ __forceinline__ void mma_f16(float c[4],
                                        unsigned a0, unsigned a1, unsigned a2, unsigned a3,
                                        unsigned b0, unsigned b1) {
    asm volatile(
        "mma.sync.aligned.m16n8k16.row.col.f32.f16.f16.f32 "
        "{%0,%1,%2,%3}, {%4,%5,%6,%7}, {%8,%9}, {%0,%1,%2,%3};"
        : "+f"(c[0]), "+f"(c[1]), "+f"(c[2]), "+f"(c[3])
        : "r"(a0), "r"(a1), "r"(a2), "r"(a3), "r"(b0), "r"(b1));
}
__device__ __forceinline__ unsigned smem_u32(const void* p) {
    unsigned a;
    asm("{ .reg .u64 t; cvta.to.shared.u64 t, %1; cvt.u32.u64 %0, t; }" : "=r"(a) : "l"(p));
    return a;
}

// A tile addressing: logical row r (0..127) = 64B, packed 2 rows per 128B phys row.
// granule slot g (0..3, 16B each) swizzled by (r>>1)&3.
__device__ __forceinline__ unsigned a_addr(int r, int g) {
    return (unsigned)(((r >> 1) * 128) + ((r & 1) * 64) + ((g ^ ((r >> 1) & 3)) << 4));
}

// ---------- merged prep: bias init + W fp16 fragment build ----------
__global__ __launch_bounds__(256) void prep_kernel(
    const float* __restrict__ Wg, const float* __restrict__ bias,
    float4* __restrict__ out) {
    const int bid = blockIdx.x;
    const int t = threadIdx.x;
    if (bid < BIAS_BLOCKS) {
        int idx = bid * 256 + t;
        float4 b = __ldg(((const float4*)bias) + (idx & 7));
        out[idx] = b;
        return;
    }
    const int ko = bid - BIAS_BLOCKS;
    const float* w = Wg + ko * 1024;
    if (t < 128) {
        int ng = t >> 5, lane = t & 31;
        int q = lane & 3;
        int n = ng * 8 + (lane >> 2);
        unsigned b[4];
#pragma unroll
        for (int kg = 0; kg < 2; kg++) {
            int k0 = kg * 16 + q * 2;
            b[2 * kg + 0] = pk_f16(__ldg(w + (k0 + 0) * 32 + n), __ldg(w + (k0 + 1) * 32 + n));
            b[2 * kg + 1] = pk_f16(__ldg(w + (k0 + 8) * 32 + n), __ldg(w + (k0 + 9) * 32 + n));
        }
        Wfrag16[(ko * 4 + ng) * 32 + lane] = make_uint4(b[0], b[1], b[2], b[3]);
    }
}

// ---------- per-subtile compute + scatter (warp-local, no block sync) ----------
__device__ __forceinline__ void compute_tile(
    char* A, const int* dst_s, const uint4 bf[4],
    float* __restrict__ out, int lane, int wid) {

    const unsigned asb = smem_u32(A);
    const int mrow = ((lane >> 3) & 1) * 8 + (lane & 7);
    const int csel = lane >> 4;
    const int qr = lane >> 2;
    const int qq = lane & 3;
    const int wbase = wid * 32;

    // load ALL A fragments first (A region reused for C after)
    unsigned af[2][2][4];                // [mg][kg][4]
#pragma unroll
    for (int mg = 0; mg < 2; mg++) {
#pragma unroll
        for (int kg = 0; kg < 2; kg++) {
            int row = wbase + mg * 16 + mrow;
            ldsm4(af[mg][kg][0], af[mg][kg][1], af[mg][kg][2], af[mg][kg][3],
                  asb + a_addr(row, kg * 2 + csel));
        }
    }

    // 16 MMAs
    float c[2][4][4];
#pragma unroll
    for (int mg = 0; mg < 2; mg++)
#pragma unroll
        for (int ng = 0; ng < 4; ng++) {
#pragma unroll
            for (int i = 0; i < 4; i++) c[mg][ng][i] = 0.0f;
            mma_f16(c[mg][ng], af[mg][0][0], af[mg][0][1], af[mg][0][2], af[mg][0][3],
                    bf[ng].x, bf[ng].y);
            mma_f16(c[mg][ng], af[mg][1][0], af[mg][1][1], af[mg][1][2], af[mg][1][3],
                    bf[ng].z, bf[ng].w);
        }

    // per mg: stage C into warp's (consumed) A region, then scatter
    char* Cw = A + wid * 2048;           // 16 phys rows x 128B
    __syncwarp();
#pragma unroll
    for (int mg = 0; mg < 2; mg++) {
        const int mgbase = wbase + mg * 16;
#pragma unroll
        for (int ng = 0; ng < 4; ng++) {
            int chunk = ng * 2 + (qq >> 1);
            int sub = (qq & 1) * 8;
            *(float2*)(Cw + qr * 128 + ((chunk ^ qr) << 4) + sub) =
                make_float2(c[mg][ng][0], c[mg][ng][1]);
            *(float2*)(Cw + (qr + 8) * 128 + ((chunk ^ qr) << 4) + sub) =
                make_float2(c[mg][ng][2], c[mg][ng][3]);
        }
        __syncwarp();

        // coalesced scatter: 8 lanes cover one 128B dst row
#pragma unroll
        for (int j = 0; j < 4; j++) {
            int idx = j * 32 + lane;     // 128 = 16 rows x 8 chunks
            int lr = idx >> 3;
            int q = idx & 7;
            int cc = q ^ (lr & 7);
            float4 v = *(const float4*)(Cw + lr * 128 + q * 16);
            red4(out + (size_t)dst_s[mgbase + lr] * COUT + cc * 4, v.x, v.y, v.z, v.w);
        }
        __syncwarp();
    }
}

// ---------- main conv: two pipelined 128-pair subtiles per block ----------
__global__ __launch_bounds__(TPB, 5) void conv_f16_kernel(
    const float4* __restrict__ in_f4,
    const int2*   __restrict__ nbmap2,
    float*        __restrict__ out) {

    __shared__ __align__(128) char A0_s[64 * 128];   // 8KB
    __shared__ __align__(128) char A1_s[64 * 128];   // 8KB
    __shared__ int src_s[TILE];
    __shared__ int dst_s[TILE];

    const int t = threadIdx.x;
    const int lane = t & 31;
    const int wid = t >> 5;
    const int ko = blockIdx.y;
    const long base = (long)ko * PPK + (long)blockIdx.x * TILE;

    // nbmap for both subtiles
    {
        int2 a = __ldg(nbmap2 + base + t);
        int2 b = __ldg(nbmap2 + base + TPB + t);
        src_s[t] = a.x;        dst_s[t] = a.y;
        src_s[TPB + t] = b.x;  dst_s[TPB + t] = b.y;
    }

    // W fragments (registers for whole kernel)
    uint4 bf[4];
#pragma unroll
    for (int ng = 0; ng < 4; ng++)
        bf[ng] = __ldg(&Wfrag16[(ko * 4 + ng) * 32 + lane]);
    __syncthreads();

    // ---- gather subtile 0 -> A0 ----
#pragma unroll
    for (int j = 0; j < 8; j++) {
        int idx = j * TPB + t;
        int r = idx >> 3;
        int c = idx & 7;
        float4 v = __ldg(in_f4 + (size_t)src_s[r] * 8 + c);
        *(uint2*)(A0_s + a_addr(r, c >> 1) + (c & 1) * 8) =
            make_uint2(pk_f16(v.x, v.y), pk_f16(v.z, v.w));
    }
    __syncthreads();

    // ---- issue gather of subtile 1 (in flight during compute 0) ----
    float4 g[8];
#pragma unroll
    for (int j = 0; j < 8; j++) {
        int idx = j * TPB + t;
        int r = (idx >> 3) + TPB;        // rows 128..255
        int c = idx & 7;
        g[j] = __ldg(in_f4 + (size_t)src_s[r] * 8 + c);
    }

    // ---- compute + scatter subtile 0 (hides gather-1 latency) ----
    compute_tile(A0_s, dst_s, bf, out, lane, wid);

    // ---- store subtile 1 -> A1 ----
#pragma unroll
    for (int j = 0; j < 8; j++) {
        int idx = j * TPB + t;
        int r = idx >> 3;                // local row in A1
        int c = idx & 7;
        *(uint2*)(A1_s + a_addr(r, c >> 1) + (c & 1) * 8) =
            make_uint2(pk_f16(g[j].x, g[j].y), pk_f16(g[j].z, g[j].w));
    }
    __syncthreads();

    // ---- compute + scatter subtile 1 ----
    compute_tile(A1_s, dst_s + TPB, bf, out, lane, wid);
}

extern "C" void kernel_launch(void* const* d_in, const int* in_sizes, int n_in,
                              void* d_out, int out_size) {
    const float* in_f  = (const float*)d_in[0];   // [262144, 32] f32
    const float* W     = (const float*)d_in[1];   // [27, 32, 32] f32
    const float* bias  = (const float*)d_in[2];   // [32] f32
    const int*   nbmap = (const int*)d_in[3];     // [M, 2] i32
    float*       out   = (float*)d_out;           // [262144, 32] f32
    (void)in_sizes; (void)n_in; (void)out_size;

    prep_kernel<<<BIAS_BLOCKS + K3, 256>>>(W, bias, (float4*)out);

    dim3 grid(PPK / TILE, K3);
    conv_f16_kernel<<<grid, TPB>>>((const float4*)in_f, (const int2*)nbmap, out);
}

// round 13
// speedup vs baseline: 1.7078x; 1.0475x over previous
#include <cuda_runtime.h>
#include <cstdint>
#include <cstddef>

#define K3   27
#define PPK  131072
#define NVOX 262144
#define CIN  32
#define COUT 32
#define TPB  128
#define TILE 256      // two 128-pair subtiles per block (pipelined)
#define BIAS_BLOCKS 8192   // NVOX*8/256

// Pre-built fp16 mma B fragments: [ko][ng][lane] = {b0_kg0, b1_kg0, b0_kg1, b1_kg1}
__device__ __align__(16) uint4 Wfrag16[K3 * 4 * 32];

// ---------- helpers ----------
// pack (a,b) -> f16x2, a in LOW half
__device__ __forceinline__ unsigned pk_f16(float a, float b) {
    unsigned r;
    asm("cvt.rn.f16x2.f32 %0, %1, %2;" : "=r"(r) : "f"(b), "f"(a));
    return r;
}
__device__ __forceinline__ void red4(float* p, float a, float b, float c, float d) {
    asm volatile("red.global.add.v4.f32 [%0], {%1, %2, %3, %4};"
                 :: "l"(p), "f"(a), "f"(b), "f"(c), "f"(d) : "memory");
}
__device__ __forceinline__ void ldsm4(unsigned &r0, unsigned &r1, unsigned &r2, unsigned &r3,
                                      unsigned addr) {
    asm volatile("ldmatrix.sync.aligned.m8n8.x4.shared.b16 {%0,%1,%2,%3}, [%4];"
                 : "=r"(r0), "=r"(r1), "=r"(r2), "=r"(r3) : "r"(addr));
}
__device__ __forceinline__ void mma_f16(float c[4],
                                        unsigned a0, unsigned a1, unsigned a2, unsigned a3,
                                        unsigned b0, unsigned b1) {
    asm volatile(
        "mma.sync.aligned.m16n8k16.row.col.f32.f16.f16.f32 "
        "{%0,%1,%2,%3}, {%4,%5,%6,%7}, {%8,%9}, {%0,%1,%2,%3};"
        : "+f"(c[0]), "+f"(c[1]), "+f"(c[2]), "+f"(c[3])
        : "r"(a0), "r"(a1), "r"(a2), "r"(a3), "r"(b0), "r"(b1));
}
__device__ __forceinline__ unsigned smem_u32(const void* p) {
    unsigned a;
    asm("{ .reg .u64 t; cvta.to.shared.u64 t, %1; cvt.u32.u64 %0, t; }" : "=r"(a) : "l"(p));
    return a;
}

// A tile addressing: logical row r (0..127) = 64B, packed 2 rows per 128B phys row.
// granule slot g (0..3, 16B each) swizzled by (r>>1)&3.
__device__ __forceinline__ unsigned a_addr(int r, int g) {
    return (unsigned)(((r >> 1) * 128) + ((r & 1) * 64) + ((g ^ ((r >> 1) & 3)) << 4));
}

// ---------- merged prep: bias init + W fp16 fragment build ----------
__global__ __launch_bounds__(256) void prep_kernel(
    const float* __restrict__ Wg, const float* __restrict__ bias,
    float4* __restrict__ out) {
    const int bid = blockIdx.x;
    const int t = threadIdx.x;
    if (bid < BIAS_BLOCKS) {
        int idx = bid * 256 + t;
        float4 b = __ldg(((const float4*)bias) + (idx & 7));
        out[idx] = b;
        return;
    }
    const int ko = bid - BIAS_BLOCKS;
    const float* w = Wg + ko * 1024;
    if (t < 128) {
        int ng = t >> 5, lane = t & 31;
        int q = lane & 3;
        int n = ng * 8 + (lane >> 2);
        unsigned b[4];
#pragma unroll
        for (int kg = 0; kg < 2; kg++) {
            int k0 = kg * 16 + q * 2;
            b[2 * kg + 0] = pk_f16(__ldg(w + (k0 + 0) * 32 + n), __ldg(w + (k0 + 1) * 32 + n));
            b[2 * kg + 1] = pk_f16(__ldg(w + (k0 + 8) * 32 + n), __ldg(w + (k0 + 9) * 32 + n));
        }
        Wfrag16[(ko * 4 + ng) * 32 + lane] = make_uint4(b[0], b[1], b[2], b[3]);
    }
}

// ---------- per-subtile compute + scatter ----------
// Reads A-fragments from A; stages C in Cbuf (the OTHER subtile buffer, idle now).
// mg-tiles fully sequential: only 8 frag regs + 16 accum regs live.
__device__ __forceinline__ void compute_tile(
    char* A, char* Cbuf, const int* dst_s, const uint4 bf[4],
    float* __restrict__ out, int lane, int wid) {

    const unsigned asb = smem_u32(A);
    const int mrow = ((lane >> 3) & 1) * 8 + (lane & 7);
    const int csel = lane >> 4;
    const int qr = lane >> 2;
    const int qq = lane & 3;
    const int wbase = wid * 32;
    char* Cw = Cbuf + wid * 2048;        // 16 phys rows x 128B, warp-private

#pragma unroll
    for (int mg = 0; mg < 2; mg++) {
        const int mgbase = wbase + mg * 16;
        const int row = mgbase + mrow;

        // A fragments for this mg only
        unsigned af[2][4];
#pragma unroll
        for (int kg = 0; kg < 2; kg++)
            ldsm4(af[kg][0], af[kg][1], af[kg][2], af[kg][3],
                  asb + a_addr(row, kg * 2 + csel));

        // 8 MMAs
        float c[4][4];
#pragma unroll
        for (int ng = 0; ng < 4; ng++) {
#pragma unroll
            for (int i = 0; i < 4; i++) c[ng][i] = 0.0f;
            mma_f16(c[ng], af[0][0], af[0][1], af[0][2], af[0][3], bf[ng].x, bf[ng].y);
            mma_f16(c[ng], af[1][0], af[1][1], af[1][2], af[1][3], bf[ng].z, bf[ng].w);
        }

        // stage C into Cbuf (other buffer -> A intact for next mg)
#pragma unroll
        for (int ng = 0; ng < 4; ng++) {
            int chunk = ng * 2 + (qq >> 1);
            int sub = (qq & 1) * 8;
            *(float2*)(Cw + qr * 128 + ((chunk ^ qr) << 4) + sub) =
                make_float2(c[ng][0], c[ng][1]);
            *(float2*)(Cw + (qr + 8) * 128 + ((chunk ^ qr) << 4) + sub) =
                make_float2(c[ng][2], c[ng][3]);
        }
        __syncwarp();

        // coalesced scatter: 8 lanes cover one 128B dst row
#pragma unroll
        for (int j = 0; j < 4; j++) {
            int idx = j * 32 + lane;     // 128 = 16 rows x 8 chunks
            int lr = idx >> 3;
            int q = idx & 7;
            int cc = q ^ (lr & 7);
            float4 v = *(const float4*)(Cw + lr * 128 + q * 16);
            red4(out + (size_t)dst_s[mgbase + lr] * COUT + cc * 4, v.x, v.y, v.z, v.w);
        }
        __syncwarp();
    }
}

// ---------- main conv: two pipelined 128-pair subtiles per block ----------
__global__ __launch_bounds__(TPB, 6) void conv_f16_kernel(
    const float4* __restrict__ in_f4,
    const int2*   __restrict__ nbmap2,
    float*        __restrict__ out) {

    __shared__ __align__(128) char A0_s[64 * 128];   // 8KB
    __shared__ __align__(128) char A1_s[64 * 128];   // 8KB
    __shared__ int src_s[TILE];
    __shared__ int dst_s[TILE];

    const int t = threadIdx.x;
    const int lane = t & 31;
    const int wid = t >> 5;
    const int ko = blockIdx.y;
    const long base = (long)ko * PPK + (long)blockIdx.x * TILE;

    // nbmap for both subtiles
    {
        int2 a = __ldg(nbmap2 + base + t);
        int2 b = __ldg(nbmap2 + base + TPB + t);
        src_s[t] = a.x;        dst_s[t] = a.y;
        src_s[TPB + t] = b.x;  dst_s[TPB + t] = b.y;
    }

    // W fragments (registers for whole kernel)
    uint4 bf[4];
#pragma unroll
    for (int ng = 0; ng < 4; ng++)
        bf[ng] = __ldg(&Wfrag16[(ko * 4 + ng) * 32 + lane]);
    __syncthreads();

    // ---- gather subtile 0 -> A0 ----
#pragma unroll
    for (int j = 0; j < 8; j++) {
        int idx = j * TPB + t;
        int r = idx >> 3;
        int c = idx & 7;
        float4 v = __ldg(in_f4 + (size_t)src_s[r] * 8 + c);
        *(uint2*)(A0_s + a_addr(r, c >> 1) + (c & 1) * 8) =
            make_uint2(pk_f16(v.x, v.y), pk_f16(v.z, v.w));
    }
    __syncthreads();

    // ---- issue gather of subtile 1 (in flight during compute 0) ----
    float4 g[8];
#pragma unroll
    for (int j = 0; j < 8; j++) {
        int idx = j * TPB + t;
        int r = (idx >> 3) + TPB;        // rows 128..255
        int c = idx & 7;
        g[j] = __ldg(in_f4 + (size_t)src_s[r] * 8 + c);
    }

    // ---- compute + scatter subtile 0 (C staged in idle A1; hides gather-1) ----
    compute_tile(A0_s, A1_s, dst_s, bf, out, lane, wid);
    __syncthreads();                     // all warps done reading A1-staged C

    // ---- store subtile 1 -> A1 ----
#pragma unroll
    for (int j = 0; j < 8; j++) {
        int idx = j * TPB + t;
        int r = idx >> 3;                // local row in A1
        int c = idx & 7;
        *(uint2*)(A1_s + a_addr(r, c >> 1) + (c & 1) * 8) =
            make_uint2(pk_f16(g[j].x, g[j].y), pk_f16(g[j].z, g[j].w));
    }
    __syncthreads();

    // ---- compute + scatter subtile 1 (C staged in dead A0) ----
    compute_tile(A1_s, A0_s, dst_s + TPB, bf, out, lane, wid);
}

extern "C" void kernel_launch(void* const* d_in, const int* in_sizes, int n_in,
                              void* d_out, int out_size) {
    const float* in_f  = (const float*)d_in[0];   // [262144, 32] f32
    const float* W     = (const float*)d_in[1];   // [27, 32, 32] f32
    const float* bias  = (const float*)d_in[2];   // [32] f32
    const int*   nbmap = (const int*)d_in[3];     // [M, 2] i32
    float*       out   = (float*)d_out;           // [262144, 32] f32
    (void)in_sizes; (void)n_in; (void)out_size;

    prep_kernel<<<BIAS_BLOCKS + K3, 256>>>(W, bias, (float4*)out);

    dim3 grid(PPK / TILE, K3);
    conv_f16_kernel<<<grid, TPB>>>((const float4*)in_f, (const int2*)nbmap, out);
}